// round 16
// baseline (speedup 1.0000x reference)
#include <cuda_runtime.h>
#include <cstdint>

// Problem constants
#define BB    8192
#define TT    100
#define TGTN  60

#define NT    256     // threads per CTA (8 warps)
#define GRID  296     // 2 x 148 SMs -> perfectly balanced 2 CTAs/SM
#define NBIG  200     // first 200 CTAs take 28 rows, rest 27 (200*28+96*27=8192)
#define BRMX  28      // max rows per CTA
#define RH    14      // rows per half (rb)
#define HPAD  36      // h row stride (floats)
#define CPAD  32      // c row stride (floats)
#define XPAD  32      // x/feedback row stride (floats)
#define CHUNKF 4096   // one weight buffer: [128 j][4 kk][4 g][2 dup] floats (16KB)

// Shared layout (float offsets, all 16B-aligned)
#define OFF_H0   0                 // [128][36] (slots 0..13,16..29 used)
#define OFF_H1   4608
#define OFF_C0   9216              // [128][32]
#define OFF_C1   13312
#define OFF_WBUF 17408             // 2 x CHUNKF (per-warp 2KB slices)
#define OFF_XS   25600             // [16][32]
#define OFF_FC   26112             // fcW [2][128]
#define OFF_FCB  26368             // fcb [2] + pad
#define SMEM_FLOATS 26372
#define SMEM_BYTES  (SMEM_FLOATS*4)   // 105,488 B -> 2 CTAs/SM

// Packed (duplicated) weights: 6 big matrices [32 chunks] + eWih0 [4] + dWih0-padded [2]
#define PACK_M   131072            // floats per big matrix (32 x 4096)
#define OFF_PIH0 (6*PACK_M)        // 786432
#define OFF_PDW  (OFF_PIH0 + 4*CHUNKF)   // 802816
#define PACK_TOT (OFF_PDW + 2*CHUNKF)    // 811008 floats (3.1MB)
__device__ float g_wpack[PACK_TOT];

typedef unsigned long long u64;

// ---- packed f32x2 helpers ----
__device__ __forceinline__ u64 f2fma(u64 a, u64 b, u64 c) {
    u64 d; asm("fma.rn.f32x2 %0, %1, %2, %3;" : "=l"(d) : "l"(a), "l"(b), "l"(c)); return d;
}
__device__ __forceinline__ u64 pk2(float x) {
    u64 r; asm("mov.b64 %0, {%1, %1};" : "=l"(r) : "f"(x)); return r;
}
__device__ __forceinline__ float2 up2(u64 v) {
    float2 f; asm("mov.b64 {%0, %1}, %2;" : "=f"(f.x), "=f"(f.y) : "l"(v)); return f;
}

// ---- activations ----
__device__ __forceinline__ float sigm(float x) {
    return __fdividef(1.0f, 1.0f + __expf(-x));
}
__device__ __forceinline__ float tanh_(float x) {
    float a = fabsf(x);
    float e = __expf(-2.0f * a);
    float t = __fdividef(1.0f - e, 1.0f + e);
    return copysignf(t, x);
}

// ---- prologue: repack weights duplicated + gate-interleaved + bank-swizzled:
//      pack[c][j][kk][g][d] = W[(g*128+j)][c*4 + (kk ^ (j&3))]  (d = 0,1 same) ----
__global__ void repack_kernel(const float* __restrict__ eWhh0, const float* __restrict__ eWih1,
                              const float* __restrict__ eWhh1, const float* __restrict__ dWhh0,
                              const float* __restrict__ dWih1, const float* __restrict__ dWhh1,
                              const float* __restrict__ eWih0, const float* __restrict__ dWih0)
{
    int idx = blockIdx.x * 256 + threadIdx.x;
    if (idx >= PACK_TOT) return;
    int within = idx & 4095;
    int j  = within >> 5;
    int kk = (within >> 3) & 3;
    int g  = (within >> 1) & 3;
    int kin = kk ^ (j & 3);
    if (idx < 6 * PACK_M) {
        int m = idx >> 17;
        int c = (idx >> 12) & 31;
        int k = (c << 2) + kin;
        const float* W = m == 0 ? eWhh0 : m == 1 ? eWih1 : m == 2 ? eWhh1
                       : m == 3 ? dWhh0 : m == 4 ? dWih1 : dWhh1;
        g_wpack[idx] = W[(g * 128 + j) * 128 + k];
    } else if (idx < OFF_PDW) {
        int c = (idx >> 12) & 3;
        int k = (c << 2) + kin;
        g_wpack[idx] = eWih0[(g * 128 + j) * 16 + k];
    } else {
        int c = (idx >> 12) & 1;
        int k = (c << 2) + kin;
        g_wpack[idx] = (k < 2) ? dWih0[(g * 128 + j) * 2 + k] : 0.0f;
    }
}

__device__ __forceinline__ void init_acc(u64 acc[4][7], const float b[4])
{
#pragma unroll
    for (int g = 0; g < 4; g++) {
        u64 bb = pk2(b[g]);
#pragma unroll
        for (int p = 0; p < 7; p++) acc[g][p] = bb;
    }
}

// ---- per-WARP cp.async of this warp's 2KB slice of one 16KB chunk ----
__device__ __forceinline__ void issue_slice(const float* __restrict__ base, int c, int buf,
                                            uint32_t smem_u32, uint32_t boff)
{
    uint32_t dst = smem_u32 + (uint32_t)((OFF_WBUF + buf * CHUNKF) * 4) + boff;
    const char* src = (const char*)(base + c * CHUNKF) + boff;
#pragma unroll
    for (int i = 0; i < 4; i++)
        asm volatile("cp.async.cg.shared.global [%0], [%1], 16;"
                     :: "r"(dst + (uint32_t)(i * 512)), "l"(src + i * 512));
    asm volatile("cp.async.commit_group;" ::: "memory");
}

// ---- streamed GEMM over K = NCH*4 (4 k-slices per 16KB chunk), per-warp
//      self-synchronized pipeline. Weights arrive as ready f32x2 broadcast
//      pairs: per k, 2x LDS.128, zero MOVs. NO __syncthreads inside. ----
template<int NCH, int STRIDE>
__device__ __forceinline__ void gemm_cp(u64 acc[4][7],
                                        const float* __restrict__ Wp,
                                        const float* __restrict__ nextWp,
                                        const float* __restrict__ hb,
                                        const char* __restrict__ smc,
                                        uint32_t smem_u32, uint32_t boff,
                                        uint32_t jx32, int j)
{
#pragma unroll 1
    for (int c = 0; c < NCH; c++) {
        asm volatile("cp.async.wait_group 0;" ::: "memory");
        __syncwarp();                    // own slice visible warp-wide; own buf free
        if (c + 1 < NCH)      issue_slice(Wp, c + 1, (c + 1) & 1, smem_u32, boff);
        else if (nextWp)      issue_slice(nextWp, 0, 0, smem_u32, boff);
        const uint32_t wbx = ((uint32_t)((OFF_WBUF + (c & 1) * CHUNKF) * 4) + (uint32_t)(j << 7)) ^ jx32;
        const float* hc = hb + c * 4 * STRIDE;
#pragma unroll
        for (int kk = 0; kk < 4; kk++) {
            uint32_t ad = wbx ^ (uint32_t)(kk << 5);
            ulonglong2 w01 = *(const ulonglong2*)(smc + ad);
            ulonglong2 w23 = *(const ulonglong2*)(smc + ad + 16);
            const float* hk = hc + kk * STRIDE;
            ulonglong2 q0 = ((const ulonglong2*)hk)[0];
            ulonglong2 q1 = ((const ulonglong2*)hk)[1];
            ulonglong2 q2 = ((const ulonglong2*)hk)[2];
            u64 a6 = ((const u64*)hk)[6];
            u64 a[7] = {q0.x, q0.y, q1.x, q1.y, q2.x, q2.y, a6};
#pragma unroll
            for (int p = 0; p < 7; p++) {
                acc[0][p] = f2fma(a[p], w01.x, acc[0][p]);
                acc[1][p] = f2fma(a[p], w01.y, acc[1][p]);
                acc[2][p] = f2fma(a[p], w23.x, acc[2][p]);
                acc[3][p] = f2fma(a[p], w23.y, acc[3][p]);
            }
        }
    }
}

// ---- LSTM pointwise epilogue: unit j, 14 rows at half rb; c in smem ----
__device__ __forceinline__ void epilogue(u64 acc[4][7],
                                         float* __restrict__ cs,
                                         float* __restrict__ hs,
                                         int j, int rb)
{
    float2* cp = (float2*)(cs + j * CPAD + rb * 16);
    float2* hp = (float2*)(hs + j * HPAD + rb * 16);
#pragma unroll
    for (int p = 0; p < 7; p++) {
        float2 gi = up2(acc[0][p]);
        float2 gf = up2(acc[1][p]);
        float2 gg = up2(acc[2][p]);
        float2 go = up2(acc[3][p]);
        float2 c = cp[p];
        float cn0 = sigm(gf.x) * c.x + sigm(gi.x) * tanh_(gg.x);
        float cn1 = sigm(gf.y) * c.y + sigm(gi.y) * tanh_(gg.y);
        cp[p] = make_float2(cn0, cn1);
        hp[p] = make_float2(sigm(go.x) * tanh_(cn0), sigm(go.y) * tanh_(cn1));
    }
}

__global__ void __launch_bounds__(NT, 2)
lstm_traj_kernel(const float* __restrict__ x,
                 const float* __restrict__ ebih0, const float* __restrict__ ebhh0,
                 const float* __restrict__ ebih1, const float* __restrict__ ebhh1,
                 const float* __restrict__ dbih0, const float* __restrict__ dbhh0,
                 const float* __restrict__ dbih1, const float* __restrict__ dbhh1,
                 const float* __restrict__ fcW,  const float* __restrict__ fcb,
                 float* __restrict__ out)
{
    extern __shared__ float sm[];
    const char* smc = (const char*)sm;
    uint32_t smem_u32 = (uint32_t)__cvta_generic_to_shared(sm);
    const int tid = threadIdx.x;
    const int j  = tid >> 1;            // hidden unit 0..127
    const int rb = tid & 1;             // row half: slots rb*16 .. rb*16+13
    const uint32_t jx32 = (uint32_t)((j & 3) << 5);
    const uint32_t boff = (uint32_t)(((tid >> 5) << 11) | ((tid & 31) << 4));  // warp-slice byte offset
    const int bid = blockIdx.x;
    const int nrows = (bid < NBIG) ? 28 : 27;
    const int gr0 = (bid < NBIG) ? bid * 28 : NBIG * 28 + (bid - NBIG) * 27;

    // biases, combined, in registers
    float be0[4], be1[4], bd0[4], bd1[4];
#pragma unroll
    for (int g = 0; g < 4; g++) {
        int idx = g * 128 + j;
        be0[g] = ebih0[idx] + ebhh0[idx];
        be1[g] = ebih1[idx] + ebhh1[idx];
        bd0[g] = dbih0[idx] + dbhh0[idx];
        bd1[g] = dbih1[idx] + dbhh1[idx];
    }

    // zero h & c states; stage FC weights
    for (int i = tid; i < OFF_WBUF; i += NT) sm[i] = 0.0f;
    sm[OFF_FC + tid] = fcW[tid];
    if (tid < 2) sm[OFF_FCB + tid] = fcb[tid];

    // stage xs for t=0
    for (int e = tid; e < 16 * BRMX; e += NT) {
        int r = e >> 4, k = e & 15;
        int slot = r + ((r >= RH) ? 2 : 0);
        int rr = (r < nrows) ? r : (nrows - 1);
        sm[OFF_XS + k * XPAD + slot] = x[(size_t)(gr0 + rr) * (TT * 16) + k];
    }
    __syncthreads();

    const float* hb0 = sm + OFF_H0 + rb * 16;
    const float* hb1 = sm + OFF_H1 + rb * 16;
    const float* xb  = sm + OFF_XS + rb * 16;

    // packed weight bases
    const float* pWhh0  = g_wpack + 0 * PACK_M;
    const float* pWih1  = g_wpack + 1 * PACK_M;
    const float* pWhh1  = g_wpack + 2 * PACK_M;
    const float* pdWhh0 = g_wpack + 3 * PACK_M;
    const float* pdWih1 = g_wpack + 4 * PACK_M;
    const float* pdWhh1 = g_wpack + 5 * PACK_M;
    const float* pWih0  = g_wpack + OFF_PIH0;
    const float* pdWih0 = g_wpack + OFF_PDW;

    // prime the per-warp pipeline: ih0 chunk 0 into buf0
    issue_slice(pWih0, 0, 0, smem_u32, boff);

    // ======================= ENCODER =======================
#pragma unroll 1
    for (int t = 0; t < TT; t++) {
        u64 acc[4][7];
        // layer 0 (reads xs, h0; no cross-warp sync inside)
        init_acc(acc, be0);
        gemm_cp<4, XPAD>(acc, pWih0, pWhh0, xb, smc, smem_u32, boff, jx32, j);
        gemm_cp<32, HPAD>(acc, pWhh0, pWih1, hb0, smc, smem_u32, boff, jx32, j);
        __syncthreads();                 // all warps done reading h0/xs
        // stage xs for t+1 early (hides LDG behind epilogue0 + layer-1 gemms)
        if (t < TT - 1) {
            for (int e = tid; e < 16 * BRMX; e += NT) {
                int r = e >> 4, k = e & 15;
                int slot = r + ((r >= RH) ? 2 : 0);
                int rr = (r < nrows) ? r : (nrows - 1);
                sm[OFF_XS + k * XPAD + slot] = x[(size_t)(gr0 + rr) * (TT * 16) + (t + 1) * 16 + k];
            }
        }
        epilogue(acc, sm + OFF_C0, sm + OFF_H0, j, rb);
        __syncthreads();                 // new h0 visible
        // layer 1
        init_acc(acc, be1);
        gemm_cp<32, HPAD>(acc, pWih1, pWhh1, hb0, smc, smem_u32, boff, jx32, j);
        gemm_cp<32, HPAD>(acc, pWhh1, (t < TT - 1) ? pWih0 : pdWih0, hb1, smc, smem_u32, boff, jx32, j);
        __syncthreads();                 // all warps done reading h1
        epilogue(acc, sm + OFF_C1, sm + OFF_H1, j, rb);
        __syncthreads();                 // h1 + xs visible
    }

    // ======================= DECODER setup =======================
    if (tid < BRMX) {   // dec_in = x[:, 99, :2]
        int r = tid;
        int slot = r + ((r >= RH) ? 2 : 0);
        int rr = (r < nrows) ? r : (nrows - 1);
        size_t base = (size_t)(gr0 + rr) * (TT * 16) + 99 * 16;
        sm[OFF_XS + slot]        = x[base + 0];
        sm[OFF_XS + XPAD + slot] = x[base + 1];
    }
    __syncthreads();

    // ======================= DECODER =======================
#pragma unroll 1
    for (int t = 0; t < TGTN; t++) {
        u64 acc[4][7];
        // layer 0: K=8 zero-padded input (streamed, only k<2 nonzero) + K=128 recurrent
        init_acc(acc, bd0);
        gemm_cp<2, XPAD>(acc, pdWih0, pdWhh0, xb, smc, smem_u32, boff, jx32, j);
        gemm_cp<32, HPAD>(acc, pdWhh0, pdWih1, hb0, smc, smem_u32, boff, jx32, j);
        __syncthreads();                 // done reading h0/xs
        epilogue(acc, sm + OFF_C0, sm + OFF_H0, j, rb);
        __syncthreads();                 // new h0 visible
        // layer 1
        init_acc(acc, bd1);
        gemm_cp<32, HPAD>(acc, pdWih1, pdWhh1, hb0, smc, smem_u32, boff, jx32, j);
        gemm_cp<32, HPAD>(acc, pdWhh1, (t < TGTN - 1) ? pdWih0 : (const float*)nullptr,
                          hb1, smc, smem_u32, boff, jx32, j);
        __syncthreads();                 // done reading h1
        epilogue(acc, sm + OFF_C1, sm + OFF_H1, j, rb);
        __syncthreads();                 // h1 ready for FC

        // FC + output + feedback
        if (tid < 2 * BRMX) {
            int r = tid >> 1;
            int o = tid & 1;
            int slot = r + ((r >= RH) ? 2 : 0);
            float s = sm[OFF_FCB + o];
            const float* fw = sm + OFF_FC + o * 128;
            const float* hv = sm + OFF_H1 + slot;
#pragma unroll 8
            for (int jj = 0; jj < 128; jj++) s += hv[jj * HPAD] * fw[jj];
            if (r < nrows) out[((size_t)(gr0 + r) * TGTN + t) * 2 + o] = s;
            sm[OFF_XS + o * XPAD + slot] = s;
        }
        __syncthreads();                 // feedback visible before next step's K=8
    }
}

extern "C" void kernel_launch(void* const* d_in, const int* in_sizes, int n_in,
                              void* d_out, int out_size)
{
    const float* x     = (const float*)d_in[0];
    const float* eWih0 = (const float*)d_in[2];
    const float* eWhh0 = (const float*)d_in[3];
    const float* ebih0 = (const float*)d_in[4];
    const float* ebhh0 = (const float*)d_in[5];
    const float* eWih1 = (const float*)d_in[6];
    const float* eWhh1 = (const float*)d_in[7];
    const float* ebih1 = (const float*)d_in[8];
    const float* ebhh1 = (const float*)d_in[9];
    const float* dWih0 = (const float*)d_in[10];
    const float* dWhh0 = (const float*)d_in[11];
    const float* dbih0 = (const float*)d_in[12];
    const float* dbhh0 = (const float*)d_in[13];
    const float* dWih1 = (const float*)d_in[14];
    const float* dWhh1 = (const float*)d_in[15];
    const float* dbih1 = (const float*)d_in[16];
    const float* dbhh1 = (const float*)d_in[17];
    const float* fcW   = (const float*)d_in[18];
    const float* fcb   = (const float*)d_in[19];
    float* out = (float*)d_out;

    // 1) repack weights duplicated + gate-interleaved + bank-swizzled, chunk-major
    repack_kernel<<<(PACK_TOT + 255) / 256, 256>>>(
        eWhh0, eWih1, eWhh1, dWhh0, dWih1, dWhh1, eWih0, dWih0);

    // 2) main kernel, balanced grid (2 CTAs per SM)
    cudaFuncSetAttribute(lstm_traj_kernel,
                         cudaFuncAttributeMaxDynamicSharedMemorySize, SMEM_BYTES);
    lstm_traj_kernel<<<GRID, NT, SMEM_BYTES>>>(
        x, ebih0, ebhh0, ebih1, ebhh1,
        dbih0, dbhh0, dbih1, dbhh1,
        fcW, fcb, out);
}

// round 17
// speedup vs baseline: 1.3531x; 1.3531x over previous
#include <cuda_runtime.h>
#include <cstdint>

// Problem constants
#define BB    8192
#define TT    100
#define TGTN  60

#define NT    256     // threads per CTA (8 warps)
#define GRID  296     // 2 x 148 SMs -> perfectly balanced 2 CTAs/SM
#define NBIG  200     // first 200 CTAs take 28 rows, rest 27 (200*28+96*27=8192)
#define BRMX  28      // max rows per CTA
#define RH    14      // rows per half (rb)
#define HPAD  36      // h row stride (floats)
#define CPAD  32      // c row stride (floats)
#define XPAD  32      // x/feedback row stride (floats)
#define CHUNKF 4096   // one weight buffer: [128 j][8 kk][4 g] floats (16KB)

// Shared layout (float offsets, all 16B-aligned)
#define OFF_H0   0                 // [128][36] (slots 0..13,16..29 used)
#define OFF_H1   4608
#define OFF_C0   9216              // [128][32]
#define OFF_C1   13312
#define OFF_WBUF 17408             // 2 x CHUNKF (per-warp 2KB slices)
#define OFF_XS   25600             // [16][32]
#define OFF_FC   26112             // fcW [2][128]
#define OFF_FCB  26368             // fcb [2] + pad
#define OFF_DW   26372             // dWih0 native [512][2]
#define SMEM_FLOATS 27396
#define SMEM_BYTES  (SMEM_FLOATS*4)   // 109,584 B -> 2 CTAs/SM

// Packed-weight scratch: 6 big matrices [16 chunks][128][8][4] + eWih0 [2 chunks][128][8][4]
#define PACK_M   65536
#define PACK_TOT (6*PACK_M + 2*4096)
__device__ float g_wpack[PACK_TOT];

typedef unsigned long long u64;

// ---- packed f32x2 helpers ----
__device__ __forceinline__ u64 pk2(float x) {
    u64 r; asm("mov.b64 %0, {%1, %1};" : "=l"(r) : "f"(x)); return r;
}
__device__ __forceinline__ u64 f2fma(u64 a, u64 b, u64 c) {
    u64 d; asm("fma.rn.f32x2 %0, %1, %2, %3;" : "=l"(d) : "l"(a), "l"(b), "l"(c)); return d;
}
__device__ __forceinline__ float2 up2(u64 v) {
    float2 f; asm("mov.b64 {%0, %1}, %2;" : "=f"(f.x), "=f"(f.y) : "l"(v)); return f;
}

// ---- activations: HW tanh (MUFU.TANH, sm_75+) ----
__device__ __forceinline__ float tanh_(float x) {
    float y; asm("tanh.approx.f32 %0, %1;" : "=f"(y) : "f"(x)); return y;
}
__device__ __forceinline__ float sigm(float x) {
    // sigmoid(x) = 0.5*tanh(0.5x) + 0.5
    float y; asm("tanh.approx.f32 %0, %1;" : "=f"(y) : "f"(0.5f * x));
    return fmaf(0.5f, y, 0.5f);
}

// ---- prologue: repack weights gate-interleaved + bank-swizzled, chunk-major
//      pack[c][j][kk][g] = W[(g*128+j)][c*8 + (kk ^ (j&7))] ----
__global__ void repack_kernel(const float* __restrict__ eWhh0, const float* __restrict__ eWih1,
                              const float* __restrict__ eWhh1, const float* __restrict__ dWhh0,
                              const float* __restrict__ dWih1, const float* __restrict__ dWhh1,
                              const float* __restrict__ eWih0)
{
    int idx = blockIdx.x * 256 + threadIdx.x;
    if (idx < 6 * PACK_M) {
        int m   = idx >> 16;
        int rem = idx & (PACK_M - 1);
        int c  = rem >> 12;
        int j  = (rem >> 5) & 127;
        int kk = (rem >> 2) & 7;
        int g  = rem & 3;
        int k  = kk ^ (j & 7);
        const float* W = m == 0 ? eWhh0 : m == 1 ? eWih1 : m == 2 ? eWhh1
                       : m == 3 ? dWhh0 : m == 4 ? dWih1 : dWhh1;
        g_wpack[idx] = W[(g * 128 + j) * 128 + c * 8 + k];
    } else if (idx < PACK_TOT) {
        int rem = idx - 6 * PACK_M;
        int c  = rem >> 12;
        int j  = (rem >> 5) & 127;
        int kk = (rem >> 2) & 7;
        int g  = rem & 3;
        int k  = kk ^ (j & 7);
        g_wpack[rem + 6 * PACK_M] = eWih0[(g * 128 + j) * 16 + c * 8 + k];
    }
}

__device__ __forceinline__ void init_acc(u64 acc[4][7], const float b[4])
{
#pragma unroll
    for (int g = 0; g < 4; g++) {
        u64 bb = pk2(b[g]);
#pragma unroll
        for (int p = 0; p < 7; p++) acc[g][p] = bb;
    }
}

// ---- per-WARP cp.async of this warp's 2KB slice of one chunk ----
__device__ __forceinline__ void issue_slice(const float* __restrict__ base, int c, int buf,
                                            uint32_t smem_u32, uint32_t boff)
{
    uint32_t dst = smem_u32 + (uint32_t)((OFF_WBUF + buf * CHUNKF) * 4) + boff;
    const char* src = (const char*)(base + c * CHUNKF) + boff;
#pragma unroll
    for (int i = 0; i < 4; i++)
        asm volatile("cp.async.cg.shared.global [%0], [%1], 16;"
                     :: "r"(dst + (uint32_t)(i * 512)), "l"(src + i * 512));
    asm volatile("cp.async.commit_group;" ::: "memory");
}

// ---- streamed GEMM over K = NCH*8, per-warp self-synchronized pipeline ----
template<int NCH, int STRIDE>
__device__ __forceinline__ void gemm_cp(u64 acc[4][7],
                                        const float* __restrict__ Wp,
                                        const float* __restrict__ nextWp,
                                        const float* __restrict__ hb,
                                        const char* __restrict__ smc,
                                        uint32_t smem_u32, uint32_t boff, int j)
{
    const uint32_t jx16 = (uint32_t)((j & 7) << 4);
#pragma unroll 1
    for (int c = 0; c < NCH; c++) {
        asm volatile("cp.async.wait_group 0;" ::: "memory");
        __syncwarp();                    // own slice visible warp-wide; own buf free
        if (c + 1 < NCH)      issue_slice(Wp, c + 1, (c + 1) & 1, smem_u32, boff);
        else if (nextWp)      issue_slice(nextWp, 0, 0, smem_u32, boff);
        const uint32_t wbx = (uint32_t)((OFF_WBUF + (c & 1) * CHUNKF + j * 32) * 4) ^ jx16;
        const float* hc = hb + c * 8 * STRIDE;
#pragma unroll
        for (int k = 0; k < 8; k++) {
            float4 wv = *(const float4*)(smc + (wbx ^ (uint32_t)(k << 4)));
            u64 b0 = pk2(wv.x);
            u64 b1 = pk2(wv.y);
            u64 b2 = pk2(wv.z);
            u64 b3 = pk2(wv.w);
            const float* hk = hc + k * STRIDE;
            ulonglong2 q0 = ((const ulonglong2*)hk)[0];
            ulonglong2 q1 = ((const ulonglong2*)hk)[1];
            ulonglong2 q2 = ((const ulonglong2*)hk)[2];
            u64 a6 = ((const u64*)hk)[6];
            u64 a[7] = {q0.x, q0.y, q1.x, q1.y, q2.x, q2.y, a6};
#pragma unroll
            for (int p = 0; p < 7; p++) {
                acc[0][p] = f2fma(a[p], b0, acc[0][p]);
                acc[1][p] = f2fma(a[p], b1, acc[1][p]);
                acc[2][p] = f2fma(a[p], b2, acc[2][p]);
                acc[3][p] = f2fma(a[p], b3, acc[3][p]);
            }
        }
    }
}

// ---- LSTM pointwise epilogue: unit j, 14 rows at half rb; c in smem ----
__device__ __forceinline__ void epilogue(u64 acc[4][7],
                                         float* __restrict__ cs,
                                         float* __restrict__ hs,
                                         int j, int rb)
{
    float2* cp = (float2*)(cs + j * CPAD + rb * 16);
    float2* hp = (float2*)(hs + j * HPAD + rb * 16);
#pragma unroll
    for (int p = 0; p < 7; p++) {
        float2 gi = up2(acc[0][p]);
        float2 gf = up2(acc[1][p]);
        float2 gg = up2(acc[2][p]);
        float2 go = up2(acc[3][p]);
        float2 c = cp[p];
        float cn0 = sigm(gf.x) * c.x + sigm(gi.x) * tanh_(gg.x);
        float cn1 = sigm(gf.y) * c.y + sigm(gi.y) * tanh_(gg.y);
        cp[p] = make_float2(cn0, cn1);
        hp[p] = make_float2(sigm(go.x) * tanh_(cn0), sigm(go.y) * tanh_(cn1));
    }
}

__global__ void __launch_bounds__(NT, 2)
lstm_traj_kernel(const float* __restrict__ x,
                 const float* __restrict__ ebih0, const float* __restrict__ ebhh0,
                 const float* __restrict__ ebih1, const float* __restrict__ ebhh1,
                 const float* __restrict__ dWih0,
                 const float* __restrict__ dbih0, const float* __restrict__ dbhh0,
                 const float* __restrict__ dbih1, const float* __restrict__ dbhh1,
                 const float* __restrict__ fcW,  const float* __restrict__ fcb,
                 float* __restrict__ out)
{
    extern __shared__ float sm[];
    const char* smc = (const char*)sm;
    uint32_t smem_u32 = (uint32_t)__cvta_generic_to_shared(sm);
    const int tid = threadIdx.x;
    const int j  = tid >> 1;            // hidden unit 0..127
    const int rb = tid & 1;             // row half: slots rb*16 .. rb*16+13
    const uint32_t boff = (uint32_t)(((tid >> 5) << 11) | ((tid & 31) << 4));  // warp-slice byte offset
    const int bid = blockIdx.x;
    const int nrows = (bid < NBIG) ? 28 : 27;
    const int gr0 = (bid < NBIG) ? bid * 28 : NBIG * 28 + (bid - NBIG) * 27;

    // biases, combined, in registers
    float be0[4], be1[4], bd0[4], bd1[4];
#pragma unroll
    for (int g = 0; g < 4; g++) {
        int idx = g * 128 + j;
        be0[g] = ebih0[idx] + ebhh0[idx];
        be1[g] = ebih1[idx] + ebhh1[idx];
        bd0[g] = dbih0[idx] + dbhh0[idx];
        bd1[g] = dbih1[idx] + dbhh1[idx];
    }

    // zero h & c states; stage FC weights + dWih0 (once)
    for (int i = tid; i < OFF_WBUF; i += NT) sm[i] = 0.0f;
    sm[OFF_FC + tid] = fcW[tid];
    if (tid < 2) sm[OFF_FCB + tid] = fcb[tid];
    for (int i = tid; i < 1024; i += NT) sm[OFF_DW + i] = dWih0[i];

    // stage xs for t=0
    for (int e = tid; e < 16 * BRMX; e += NT) {
        int r = e >> 4, k = e & 15;
        int slot = r + ((r >= RH) ? 2 : 0);
        int rr = (r < nrows) ? r : (nrows - 1);
        sm[OFF_XS + k * XPAD + slot] = x[(size_t)(gr0 + rr) * (TT * 16) + k];
    }
    __syncthreads();

    const float* hb0 = sm + OFF_H0 + rb * 16;
    const float* hb1 = sm + OFF_H1 + rb * 16;
    const float* xb  = sm + OFF_XS + rb * 16;

    // packed weight bases
    const float* pWhh0  = g_wpack + 0 * PACK_M;
    const float* pWih1  = g_wpack + 1 * PACK_M;
    const float* pWhh1  = g_wpack + 2 * PACK_M;
    const float* pdWhh0 = g_wpack + 3 * PACK_M;
    const float* pdWih1 = g_wpack + 4 * PACK_M;
    const float* pdWhh1 = g_wpack + 5 * PACK_M;
    const float* pWih0  = g_wpack + 6 * PACK_M;

    // prime the per-warp pipeline: ih0 chunk 0 into buf0
    issue_slice(pWih0, 0, 0, smem_u32, boff);

    // ======================= ENCODER =======================
#pragma unroll 1
    for (int t = 0; t < TT; t++) {
        u64 acc[4][7];
        // layer 0 (reads xs, h0; no cross-warp sync inside)
        init_acc(acc, be0);
        gemm_cp<2, XPAD>(acc, pWih0, pWhh0, xb, smc, smem_u32, boff, j);
        gemm_cp<16, HPAD>(acc, pWhh0, pWih1, hb0, smc, smem_u32, boff, j);
        __syncthreads();                 // all warps done reading h0/xs
        epilogue(acc, sm + OFF_C0, sm + OFF_H0, j, rb);
        __syncthreads();                 // new h0 visible
        // layer 1
        init_acc(acc, be1);
        gemm_cp<16, HPAD>(acc, pWih1, pWhh1, hb0, smc, smem_u32, boff, j);
        gemm_cp<16, HPAD>(acc, pWhh1, (t < TT - 1) ? pWih0 : pdWhh0, hb1, smc, smem_u32, boff, j);
        __syncthreads();                 // all warps done reading h1
        epilogue(acc, sm + OFF_C1, sm + OFF_H1, j, rb);
        // stage xs for t+1 (readers of xs[t] finished at pre-epi0 barrier)
        if (t < TT - 1) {
            for (int e = tid; e < 16 * BRMX; e += NT) {
                int r = e >> 4, k = e & 15;
                int slot = r + ((r >= RH) ? 2 : 0);
                int rr = (r < nrows) ? r : (nrows - 1);
                sm[OFF_XS + k * XPAD + slot] = x[(size_t)(gr0 + rr) * (TT * 16) + (t + 1) * 16 + k];
            }
        }
        __syncthreads();                 // h1 + xs visible
    }

    // ======================= DECODER setup =======================
    if (tid < BRMX) {   // dec_in = x[:, 99, :2]
        int r = tid;
        int slot = r + ((r >= RH) ? 2 : 0);
        int rr = (r < nrows) ? r : (nrows - 1);
        size_t base = (size_t)(gr0 + rr) * (TT * 16) + 99 * 16;
        sm[OFF_XS + slot]        = x[base + 0];
        sm[OFF_XS + XPAD + slot] = x[base + 1];
    }
    __syncthreads();

    // ======================= DECODER =======================
#pragma unroll 1
    for (int t = 0; t < TGTN; t++) {
        u64 acc[4][7];
        // layer 0: K=2 input from resident dW [512][2] + K=128 recurrent
        init_acc(acc, bd0);
#pragma unroll
        for (int k = 0; k < 2; k++) {
            const float* dw = sm + OFF_DW;
            u64 b0 = pk2(dw[(j      ) * 2 + k]);
            u64 b1 = pk2(dw[(j + 128) * 2 + k]);
            u64 b2 = pk2(dw[(j + 256) * 2 + k]);
            u64 b3 = pk2(dw[(j + 384) * 2 + k]);
            const float* hk = xb + k * XPAD;
            ulonglong2 q0 = ((const ulonglong2*)hk)[0];
            ulonglong2 q1 = ((const ulonglong2*)hk)[1];
            ulonglong2 q2 = ((const ulonglong2*)hk)[2];
            u64 a6 = ((const u64*)hk)[6];
            u64 a[7] = {q0.x, q0.y, q1.x, q1.y, q2.x, q2.y, a6};
#pragma unroll
            for (int p = 0; p < 7; p++) {
                acc[0][p] = f2fma(a[p], b0, acc[0][p]);
                acc[1][p] = f2fma(a[p], b1, acc[1][p]);
                acc[2][p] = f2fma(a[p], b2, acc[2][p]);
                acc[3][p] = f2fma(a[p], b3, acc[3][p]);
            }
        }
        gemm_cp<16, HPAD>(acc, pdWhh0, pdWih1, hb0, smc, smem_u32, boff, j);
        __syncthreads();                 // done reading h0/xs
        epilogue(acc, sm + OFF_C0, sm + OFF_H0, j, rb);
        __syncthreads();                 // new h0 visible
        // layer 1
        init_acc(acc, bd1);
        gemm_cp<16, HPAD>(acc, pdWih1, pdWhh1, hb0, smc, smem_u32, boff, j);
        gemm_cp<16, HPAD>(acc, pdWhh1, (t < TGTN - 1) ? pdWhh0 : (const float*)nullptr,
                          hb1, smc, smem_u32, boff, j);
        __syncthreads();                 // done reading h1
        epilogue(acc, sm + OFF_C1, sm + OFF_H1, j, rb);
        __syncthreads();                 // h1 ready for FC

        // FC + output + feedback
        if (tid < 2 * BRMX) {
            int r = tid >> 1;
            int o = tid & 1;
            int slot = r + ((r >= RH) ? 2 : 0);
            float s = sm[OFF_FCB + o];
            const float* fw = sm + OFF_FC + o * 128;
            const float* hv = sm + OFF_H1 + slot;
#pragma unroll 8
            for (int jj = 0; jj < 128; jj++) s += hv[jj * HPAD] * fw[jj];
            if (r < nrows) out[((size_t)(gr0 + r) * TGTN + t) * 2 + o] = s;
            sm[OFF_XS + o * XPAD + slot] = s;
        }
        __syncthreads();                 // feedback visible before next step's K=2
    }
}

extern "C" void kernel_launch(void* const* d_in, const int* in_sizes, int n_in,
                              void* d_out, int out_size)
{
    const float* x     = (const float*)d_in[0];
    const float* eWih0 = (const float*)d_in[2];
    const float* eWhh0 = (const float*)d_in[3];
    const float* ebih0 = (const float*)d_in[4];
    const float* ebhh0 = (const float*)d_in[5];
    const float* eWih1 = (const float*)d_in[6];
    const float* eWhh1 = (const float*)d_in[7];
    const float* ebih1 = (const float*)d_in[8];
    const float* ebhh1 = (const float*)d_in[9];
    const float* dWih0 = (const float*)d_in[10];
    const float* dWhh0 = (const float*)d_in[11];
    const float* dbih0 = (const float*)d_in[12];
    const float* dbhh0 = (const float*)d_in[13];
    const float* dWih1 = (const float*)d_in[14];
    const float* dWhh1 = (const float*)d_in[15];
    const float* dbih1 = (const float*)d_in[16];
    const float* dbhh1 = (const float*)d_in[17];
    const float* fcW   = (const float*)d_in[18];
    const float* fcb   = (const float*)d_in[19];
    float* out = (float*)d_out;

    // 1) repack weights gate-interleaved + bank-swizzled, chunk-major
    repack_kernel<<<(PACK_TOT + 255) / 256, 256>>>(
        eWhh0, eWih1, eWhh1, dWhh0, dWih1, dWhh1, eWih0);

    // 2) main kernel, balanced grid (2 CTAs per SM)
    cudaFuncSetAttribute(lstm_traj_kernel,
                         cudaFuncAttributeMaxDynamicSharedMemorySize, SMEM_BYTES);
    lstm_traj_kernel<<<GRID, NT, SMEM_BYTES>>>(
        x, ebih0, ebhh0, ebih1, ebhh1,
        dWih0, dbih0, dbhh0, dbih1, dbhh1,
        fcW, fcb, out);
}